// round 14
// baseline (speedup 1.0000x reference)
#include <cuda_runtime.h>
#include <cuda_bf16.h>
#include <stdint.h>
#include <math.h>

typedef __nv_bfloat16 bf16;

// B=16,T=12,N=2048,D=128. Arena offsets (float units). Planes: hi then lo (bf16).
static const long long OFF_S   = 0;            // S f32 67108864 ; then Up planes
static const long long OFF_SP  = 67108864LL;   // SP planes ; then ON f32
static const long long OFF_H1P = 134217728LL;
static const long long OFF_QKVP= 138412032LL;
static const long long OFF_VTP = 150994944LL;
static const long long OFF_OP  = 155189248LL;
static const long long OFF_REP = 159383552LL;  // later HR f32
static const long long OFF_IMP = 188743680LL;  // later HI f32
static const long long OFF_H2P = 218103808LL;  // 117440512
static const long long OFF_WQKVP=335544320LL;
static const long long OFF_BQKV =335593472LL;
static const long long OFF_WU1P =335593856LL;
static const long long OFF_WU2P =335790464LL;
static const long long OFF_W1AP =338149760LL;
static const long long OFF_W1BP =338182528LL;
static const long long OFF_B1A  =338215296LL;
static const long long OFF_B1B  =338215552LL;
static const long long OFF_WCRP =338215808LL;
static const long long OFF_WCIP =338248576LL;
static const long long OFF_BCR  =338281344LL;
static const long long OFF_BCI  =338281472LL;

__device__ float g_arena[338282496];

__device__ __forceinline__ float epi_f(float v, int epi) {
    if (epi == 1) return v > 0.f ? v : 0.f;
    if (epi == 2) return 0.5f * v * (1.f + erff(v * 0.7071067811865476f));
    return v;
}
__device__ __forceinline__ void split1(float a, bf16& h, bf16& l) {
    h = __float2bfloat16_rn(a);
    l = __float2bfloat16_rn(a - __bfloat162float(h));
}
__device__ __forceinline__ void split2(float a, float b, uint32_t& h, uint32_t& l) {
    bf16 ha, la, hb, lb;
    split1(a, ha, la); split1(b, hb, lb);
    h = (uint32_t)__bfloat16_as_ushort(ha) | ((uint32_t)__bfloat16_as_ushort(hb) << 16);
    l = (uint32_t)__bfloat16_as_ushort(la) | ((uint32_t)__bfloat16_as_ushort(lb) << 16);
}
__device__ __forceinline__ void ldsm4(uint32_t &r0, uint32_t &r1, uint32_t &r2, uint32_t &r3,
                                      uint32_t addr) {
    asm volatile("ldmatrix.sync.aligned.m8n8.x4.shared.b16 {%0,%1,%2,%3}, [%4];"
                 : "=r"(r0), "=r"(r1), "=r"(r2), "=r"(r3) : "r"(addr));
}
__device__ __forceinline__ void mma_bf16(float* d, const uint32_t* a, const uint32_t* b) {
    asm volatile("mma.sync.aligned.m16n8k16.row.col.f32.bf16.bf16.f32 "
                 "{%0,%1,%2,%3}, {%4,%5,%6,%7}, {%8,%9}, {%0,%1,%2,%3};"
                 : "+f"(d[0]), "+f"(d[1]), "+f"(d[2]), "+f"(d[3])
                 : "r"(a[0]), "r"(a[1]), "r"(a[2]), "r"(a[3]), "r"(b[0]), "r"(b[1]));
}
__device__ __forceinline__ void cpa16(uint32_t dst, const void* src) {
    asm volatile("cp.async.cg.shared.global [%0], [%1], 16;" :: "r"(dst), "l"(src));
}
__device__ __forceinline__ void split_pack(float4 v0, float4 v1, uint4 &hi, uint4 &lo) {
    float f[8] = {v0.x, v0.y, v0.z, v0.w, v1.x, v1.y, v1.z, v1.w};
    uint32_t h[4], l[4];
#pragma unroll
    for (int i = 0; i < 4; i++) split2(f[2*i], f[2*i+1], h[i], l[i]);
    hi = make_uint4(h[0], h[1], h[2], h[3]);
    lo = make_uint4(l[0], l[1], l[2], l[3]);
}
__device__ __forceinline__ const float* xgather_ptr(const float* X, int row, int k) {
    int t = k >> 7, d = k & 127, b = row >> 11, n = row & 2047;
    return X + ((long long)(b * 12 + t) * 2048 + n) * 128 + d;
}

// shared epilogue writer
__device__ __forceinline__ void epi_store(void* Cv, const float* bias, float acc[4][4][4],
    int bx, int by, long long bzsC, int ldc, int colstep, long long pC,
    float alpha, int epi, int omode, int t)
{
    const int lane = t & 31;
    const int wm = (t >> 7) * 64, wn = ((t >> 5) & 3) * 32;
    const int g = lane >> 2, tt = lane & 3;
    const long long rowBase = (long long)by * 128 + wm + g;
#pragma unroll
    for (int mf = 0; mf < 4; mf++) {
#pragma unroll
        for (int nf = 0; nf < 4; nf++) {
            const int nIdx = bx * 128 + wn + nf * 8 + 2 * tt;
            const int col = bx * colstep + wn + nf * 8 + 2 * tt;
            float2 bv = make_float2(0.f, 0.f);
            if (bias) bv = *(const float2*)(bias + nIdx);
            float x0 = epi_f(acc[mf][nf][0] * alpha + bv.x, epi);
            float y0 = epi_f(acc[mf][nf][1] * alpha + bv.y, epi);
            float x1 = epi_f(acc[mf][nf][2] * alpha + bv.x, epi);
            float y1 = epi_f(acc[mf][nf][3] * alpha + bv.y, epi);
            const long long r0 = (rowBase + mf * 16) * ldc + col;
            if (omode == 0) {
                float* C = (float*)Cv + bzsC;
                *(float2*)(C + r0) = make_float2(x0, y0);
                *(float2*)(C + r0 + 8LL * ldc) = make_float2(x1, y1);
            } else {
                bf16* Ch = (bf16*)Cv + bzsC;
                bf16* Cl = Ch + pC;
                uint32_t h, l;
                split2(x0, y0, h, l);
                *(uint32_t*)(Ch + r0) = h; *(uint32_t*)(Cl + r0) = l;
                split2(x1, y1, h, l);
                *(uint32_t*)(Ch + r0 + 8LL * ldc) = h; *(uint32_t*)(Cl + r0 + 8LL * ldc) = l;
            }
        }
    }
}

// ===== plane-input GEMM, 3-stage cp.async pipeline, 1 barrier/K-step =====
__global__ void __launch_bounds__(256, 2)
gemm_pl(const bf16* __restrict__ Ah, const bf16* __restrict__ Bh,
        const float* __restrict__ bias, void* __restrict__ Cv,
        int K, int lda, int ldb, int ldc, int colstep, float alpha, int epi, int omode,
        long long pA, long long pB, long long pC,
        long long sA, long long sB, long long sC)
{
    extern __shared__ __align__(16) char smc[];
    const int t = threadIdx.x;
    const int bx = blockIdx.x, by = blockIdx.y, bz = blockIdx.z;
    const int lane = t & 31;
    const uint32_t smemBase = (uint32_t)__cvta_generic_to_shared(smc);

    const int lr2 = t >> 1, hf = t & 1, s7b = lr2 & 7;
    const bf16* Agh = Ah + bz * sA + (long long)(by * 128 + lr2) * lda;
    const bf16* Agl = Agh + pA;
    const bf16* Bgh = Bh + bz * sB + (long long)(bx * 128 + lr2) * ldb;
    const bf16* Bgl = Bgh + pB;
    const uint32_t rowb = smemBase + (uint32_t)lr2 * 128;

    const int sub = lane >> 3, l7 = lane & 7;
    const int wm = (t >> 7) * 64, wn = ((t >> 5) & 3) * 32;
    const int aRowOff = wm + l7 + ((sub & 1) << 3);
    const int aSel = sub >> 1;
    const int bRowOff = wn + l7 + ((sub >> 1) << 3);
    const int bSel = sub & 1;

    float acc[4][4][4];
#pragma unroll
    for (int i = 0; i < 4; i++)
#pragma unroll
        for (int j = 0; j < 4; j++)
#pragma unroll
            for (int q = 0; q < 4; q++) acc[i][j][q] = 0.f;

    const int nk = K >> 5;
#define ISSUE(S) do { \
    const uint32_t sb = rowb + (uint32_t)((S) % 3) * 32768u; \
    const int k0 = (S) * 32; \
    _Pragma("unroll") \
    for (int j = 0; j < 2; j++) { \
        int u = hf * 2 + j; \
        cpa16(sb + (uint32_t)((u ^ s7b) << 4), Agh + k0 + u * 8); \
        cpa16(sb + (uint32_t)(((u + 4) ^ s7b) << 4), Agl + k0 + u * 8); \
        cpa16(sb + 16384u + (uint32_t)((u ^ s7b) << 4), Bgh + k0 + u * 8); \
        cpa16(sb + 16384u + (uint32_t)(((u + 4) ^ s7b) << 4), Bgl + k0 + u * 8); \
    } \
    asm volatile("cp.async.commit_group;"); \
} while (0)

    ISSUE(0);
    if (nk > 1) ISSUE(1);
    for (int s = 0; s < nk; s++) {
        if (s + 1 < nk) asm volatile("cp.async.wait_group 1;");
        else            asm volatile("cp.async.wait_group 0;");
        __syncthreads();
        if (s + 2 < nk) ISSUE(s + 2);   // writes buf (s+2)%3 == (s-1)%3: freed by barrier above
        const uint32_t stg = smemBase + (uint32_t)(s % 3) * 32768u;
#pragma unroll
        for (int kh = 0; kh < 2; kh++) {
            uint32_t ah[4][4], al[4][4], bh[4][2], bl[4][2];
#pragma unroll
            for (int mf = 0; mf < 4; mf++) {
                const uint32_t rb = stg + (uint32_t)(aRowOff + mf * 16) * 128;
                const int u0 = 2 * kh + aSel;
                ldsm4(ah[mf][0], ah[mf][1], ah[mf][2], ah[mf][3], rb + ((u0 ^ l7) << 4));
                ldsm4(al[mf][0], al[mf][1], al[mf][2], al[mf][3], rb + (((u0 + 4) ^ l7) << 4));
            }
#pragma unroll
            for (int np = 0; np < 2; np++) {
                const uint32_t rb = stg + 16384 + (uint32_t)(bRowOff + np * 16) * 128;
                const int u0 = 2 * kh + bSel;
                uint32_t r0, r1, r2, r3;
                ldsm4(r0, r1, r2, r3, rb + ((u0 ^ l7) << 4));
                bh[np*2][0] = r0; bh[np*2][1] = r1; bh[np*2+1][0] = r2; bh[np*2+1][1] = r3;
                ldsm4(r0, r1, r2, r3, rb + (((u0 + 4) ^ l7) << 4));
                bl[np*2][0] = r0; bl[np*2][1] = r1; bl[np*2+1][0] = r2; bl[np*2+1][1] = r3;
            }
#pragma unroll
            for (int mf = 0; mf < 4; mf++)
#pragma unroll
                for (int nf = 0; nf < 4; nf++) {
                    mma_bf16(acc[mf][nf], ah[mf], bh[nf]);
                    mma_bf16(acc[mf][nf], ah[mf], bl[nf]);
                    mma_bf16(acc[mf][nf], al[mf], bh[nf]);
                }
        }
    }
#undef ISSUE
    epi_store(Cv, bias, acc, bx, by, (long long)bz * sC, ldc, colstep, pC, alpha, epi, omode, t);
}

// ===== f32-input GEMM (x-gather); used only for conv_down G1 =====
__global__ void __launch_bounds__(256)
gemm_f32(const float* __restrict__ A, const float* __restrict__ B,
         const float* __restrict__ bias, void* __restrict__ Cv,
         int K, int ldb, int ldc, int colstep, float alpha, int epi, int omode, long long pC)
{
    extern __shared__ __align__(16) uint4 sm[];
    const int t = threadIdx.x;
    const int bx = blockIdx.x, by = blockIdx.y;
    const int lane = t & 31;

    const int lr = t >> 2, lc = t & 3, s7 = lr & 7;
    const float* Bg0 = B + (long long)(bx * 128 + lr) * ldb + lc * 8;
    const float* Bg1 = Bg0 + (long long)64 * ldb;

    const int sub = lane >> 3, l7 = lane & 7;
    const int wm = (t >> 7) * 64, wn = ((t >> 5) & 3) * 32;
    const int aRowOff = wm + l7 + ((sub & 1) << 3);
    const int aSel = sub >> 1;
    const int bRowOff = wn + l7 + ((sub >> 1) << 3);
    const int bSel = sub & 1;
    const uint32_t smemBase = (uint32_t)__cvta_generic_to_shared(sm);

    float acc[4][4][4];
#pragma unroll
    for (int i = 0; i < 4; i++)
#pragma unroll
        for (int j = 0; j < 4; j++)
#pragma unroll
            for (int q = 0; q < 4; q++) acc[i][j][q] = 0.f;

    const int nk = K >> 5;
    {
        const float* pa0 = xgather_ptr(A, by*128 + lr, lc*8);
        const float* pa1 = xgather_ptr(A, by*128 + lr + 64, lc*8);
        uint4 hi, lo;
        uint4* bA0 = sm + lr * 8;        uint4* bA1 = bA0 + 512;
        uint4* bB0 = sm + 1024 + lr * 8; uint4* bB1 = bB0 + 512;
        split_pack(*(const float4*)pa0, *(const float4*)(pa0+4), hi, lo);
        bA0[lc ^ s7] = hi; bA0[(lc+4) ^ s7] = lo;
        split_pack(*(const float4*)pa1, *(const float4*)(pa1+4), hi, lo);
        bA1[lc ^ s7] = hi; bA1[(lc+4) ^ s7] = lo;
        split_pack(*(const float4*)Bg0, *(const float4*)(Bg0+4), hi, lo);
        bB0[lc ^ s7] = hi; bB0[(lc+4) ^ s7] = lo;
        split_pack(*(const float4*)Bg1, *(const float4*)(Bg1+4), hi, lo);
        bB1[lc ^ s7] = hi; bB1[(lc+4) ^ s7] = lo;
    }
    __syncthreads();

    for (int s = 0; s < nk; s++) {
        float4 a00, a01, a10, a11, b00, b01, b10, b11;
        const bool more = (s + 1) < nk;
        if (more) {
            const float* pa0 = xgather_ptr(A, by*128 + lr, (s+1)*32 + lc*8);
            const float* pa1 = xgather_ptr(A, by*128 + lr + 64, (s+1)*32 + lc*8);
            const float* pb0 = Bg0 + (s+1)*32; const float* pb1 = Bg1 + (s+1)*32;
            a00 = *(const float4*)pa0; a01 = *(const float4*)(pa0+4);
            a10 = *(const float4*)pa1; a11 = *(const float4*)(pa1+4);
            b00 = *(const float4*)pb0; b01 = *(const float4*)(pb0+4);
            b10 = *(const float4*)pb1; b11 = *(const float4*)(pb1+4);
        }
        const uint32_t stg = smemBase + (uint32_t)(s & 1) * 32768u;
#pragma unroll
        for (int kh = 0; kh < 2; kh++) {
            uint32_t ah[4][4], al[4][4], bh[4][2], bl[4][2];
#pragma unroll
            for (int mf = 0; mf < 4; mf++) {
                const uint32_t rb = stg + (uint32_t)(aRowOff + mf * 16) * 128;
                const int u0 = 2 * kh + aSel;
                ldsm4(ah[mf][0], ah[mf][1], ah[mf][2], ah[mf][3], rb + ((u0 ^ l7) << 4));
                ldsm4(al[mf][0], al[mf][1], al[mf][2], al[mf][3], rb + (((u0 + 4) ^ l7) << 4));
            }
#pragma unroll
            for (int np = 0; np < 2; np++) {
                const uint32_t rb = stg + 16384 + (uint32_t)(bRowOff + np * 16) * 128;
                const int u0 = 2 * kh + bSel;
                uint32_t r0, r1, r2, r3;
                ldsm4(r0, r1, r2, r3, rb + ((u0 ^ l7) << 4));
                bh[np*2][0] = r0; bh[np*2][1] = r1; bh[np*2+1][0] = r2; bh[np*2+1][1] = r3;
                ldsm4(r0, r1, r2, r3, rb + (((u0 + 4) ^ l7) << 4));
                bl[np*2][0] = r0; bl[np*2][1] = r1; bl[np*2+1][0] = r2; bl[np*2+1][1] = r3;
            }
#pragma unroll
            for (int mf = 0; mf < 4; mf++)
#pragma unroll
                for (int nf = 0; nf < 4; nf++) {
                    mma_bf16(acc[mf][nf], ah[mf], bh[nf]);
                    mma_bf16(acc[mf][nf], ah[mf], bl[nf]);
                    mma_bf16(acc[mf][nf], al[mf], bh[nf]);
                }
        }
        if (more) {
            const uint32_t ns = (uint32_t)((s + 1) & 1);
            uint4 hi, lo;
            uint4* bA0 = sm + ns*2048 + lr * 8;        uint4* bA1 = bA0 + 512;
            uint4* bB0 = sm + ns*2048 + 1024 + lr * 8; uint4* bB1 = bB0 + 512;
            split_pack(a00, a01, hi, lo); bA0[lc ^ s7] = hi; bA0[(lc+4) ^ s7] = lo;
            split_pack(a10, a11, hi, lo); bA1[lc ^ s7] = hi; bA1[(lc+4) ^ s7] = lo;
            split_pack(b00, b01, hi, lo); bB0[lc ^ s7] = hi; bB0[(lc+4) ^ s7] = lo;
            split_pack(b10, b11, hi, lo); bB1[lc ^ s7] = hi; bB1[(lc+4) ^ s7] = lo;
        }
        __syncthreads();
    }
    epi_store(Cv, bias, acc, bx, by, 0, ldc, colstep, pC, alpha, epi, omode, t);
}

// ===== producers / prep =====
__global__ void wqkv_fold(const float* __restrict__ Wq, const float* __restrict__ bq,
                          const float* __restrict__ Wk, const float* __restrict__ bk,
                          const float* __restrict__ Wv, const float* __restrict__ bv,
                          const float* __restrict__ Wd2, const float* __restrict__ bd2,
                          bf16* __restrict__ Wh, float* __restrict__ BQKV)
{
    int i = blockIdx.x, j = threadIdx.x;
    const float* row = (i < 128) ? Wq + i * 128 : (i < 256) ? Wk + (i - 128) * 128 : Wv + (i - 256) * 128;
    float bo = (i < 128) ? bq[i] : (i < 256) ? bk[i - 128] : bv[i - 256];
    float acc = 0.f, accb = 0.f;
    for (int c = 0; c < 128; c++) {
        float w = row[c];
        acc += w * Wd2[c * 128 + j];
        accb += w * bd2[c];
    }
    bf16 h, l; split1(acc, h, l);
    Wh[i * 128 + j] = h; Wh[49152 + i * 128 + j] = l;
    if (j == 0) BQKV[i] = accb + bo;
}

__global__ void build_w1(const float* __restrict__ Wr1, const float* __restrict__ br1,
                         const float* __restrict__ Wi1, const float* __restrict__ bi1,
                         bf16* __restrict__ W1A, float* __restrict__ b1a,
                         bf16* __restrict__ W1B, float* __restrict__ b1b)
{
    int i = blockIdx.x * 256 + threadIdx.x;
    int r = i >> 7, c = i & 127;
    float va = (r < 128) ? Wr1[r * 128 + c] : Wi1[(r - 128) * 128 + c];
    float vb = (r < 128) ? Wi1[r * 128 + c] : Wr1[(r - 128) * 128 + c];
    bf16 h, l;
    split1(va, h, l); W1A[i] = h; W1A[32768 + i] = l;
    split1(vb, h, l); W1B[i] = h; W1B[32768 + i] = l;
    if (i < 256) {
        b1a[i] = (i < 128) ? br1[i] : bi1[i - 128];
        b1b[i] = (i < 128) ? bi1[i] : br1[i - 128];
    }
}

__global__ void build_wcat(const float* __restrict__ Wr2, const float* __restrict__ br2,
                           const float* __restrict__ Wi2, const float* __restrict__ bi2,
                           bf16* __restrict__ WCR, float* __restrict__ bcr,
                           bf16* __restrict__ WCI, float* __restrict__ bci)
{
    int i = blockIdx.x * 256 + threadIdx.x;
    int n = i >> 8, k = i & 255;
    float vr, vi;
    if (k < 128) { vr = Wr2[n * 128 + k];        vi = Wi2[n * 128 + k]; }
    else         { vr = -Wi2[n * 128 + k - 128]; vi = Wr2[n * 128 + k - 128]; }
    bf16 h, l;
    split1(vr, h, l); WCR[i] = h; WCR[32768 + i] = l;
    split1(vi, h, l); WCI[i] = h; WCI[32768 + i] = l;
    if (i < 128) { bcr[i] = br2[i] - bi2[i]; bci[i] = bi2[i] + br2[i]; }
}

__global__ void wconv(const float* __restrict__ W, bf16* __restrict__ Wp, int n, int plane) {
    int i = blockIdx.x * 256 + threadIdx.x;
    if (i < n) { bf16 h, l; split1(W[i], h, l); Wp[i] = h; Wp[plane + i] = l; }
}

__global__ void transpose_v(const bf16* __restrict__ Qh, const bf16* __restrict__ Ql,
                            bf16* __restrict__ VTh, bf16* __restrict__ VTl)
{
    __shared__ uint32_t tile[32][33];
    int b = blockIdx.z, n0 = blockIdx.x * 32, d0 = blockIdx.y * 32;
    int tx = threadIdx.x & 31, ty = threadIdx.x >> 5;
#pragma unroll
    for (int i = 0; i < 32; i += 8) {
        long long idx = ((long long)b * 2048 + n0 + ty + i) * 384 + 256 + d0 + tx;
        tile[ty + i][tx] = (uint32_t)__bfloat16_as_ushort(Qh[idx])
                         | ((uint32_t)__bfloat16_as_ushort(Ql[idx]) << 16);
    }
    __syncthreads();
#pragma unroll
    for (int i = 0; i < 32; i += 8) {
        uint32_t p = tile[tx][ty + i];
        long long o = (long long)b * 262144 + (long long)(d0 + ty + i) * 2048 + n0 + tx;
        VTh[o] = __ushort_as_bfloat16((unsigned short)(p & 0xffff));
        VTl[o] = __ushort_as_bfloat16((unsigned short)(p >> 16));
    }
}

__global__ void softmax2048(const float* __restrict__ S, bf16* __restrict__ Sh, bf16* __restrict__ Sl) {
    const float* row = S + (long long)blockIdx.x * 2048;
    long long obase = (long long)blockIdx.x * 2048;
    int t = threadIdx.x;
    float v[8], mx = -3.4e38f;
#pragma unroll
    for (int i = 0; i < 8; i++) { v[i] = row[t + (i << 8)]; mx = fmaxf(mx, v[i]); }
    __shared__ float red[8];
#pragma unroll
    for (int o = 16; o; o >>= 1) mx = fmaxf(mx, __shfl_xor_sync(0xffffffffu, mx, o));
    if ((t & 31) == 0) red[t >> 5] = mx;
    __syncthreads();
    mx = red[0];
#pragma unroll
    for (int i = 1; i < 8; i++) mx = fmaxf(mx, red[i]);
    float s = 0.f;
#pragma unroll
    for (int i = 0; i < 8; i++) { v[i] = __expf(v[i] - mx); s += v[i]; }
#pragma unroll
    for (int o = 16; o; o >>= 1) s += __shfl_xor_sync(0xffffffffu, s, o);
    __syncthreads();
    if ((t & 31) == 0) red[t >> 5] = s;
    __syncthreads();
    s = 0.f;
#pragma unroll
    for (int i = 0; i < 8; i++) s += red[i];
    float inv = 1.f / s;
#pragma unroll
    for (int i = 0; i < 8; i++) {
        bf16 h, l; split1(v[i] * inv, h, l);
        Sh[obase + t + (i << 8)] = h; Sl[obase + t + (i << 8)] = l;
    }
}

__global__ void ln_dft(const float* __restrict__ ON, const float* __restrict__ x,
                       const float* __restrict__ gamma, const float* __restrict__ beta,
                       bf16* __restrict__ Rh, bf16* __restrict__ Rl,
                       bf16* __restrict__ Ih, bf16* __restrict__ Il)
{
    int bn = blockIdx.x;
    int d = threadIdx.x;
    int b = bn >> 11, n = bn & 2047;
    float v[12];
    const float* onp = ON + (long long)bn * 1536 + d;
    const float* xp = x + ((long long)(b * 12) * 2048 + n) * 128 + d;
#pragma unroll
    for (int t = 0; t < 12; t++) v[t] = onp[t * 128] + xp[(long long)t * 262144];

    __shared__ float sred[12][4], qred[12][4];
    int w = d >> 5, lane = d & 31;
#pragma unroll
    for (int t = 0; t < 12; t++) {
        float s = v[t], q = v[t] * v[t];
#pragma unroll
        for (int o = 16; o; o >>= 1) {
            s += __shfl_xor_sync(0xffffffffu, s, o);
            q += __shfl_xor_sync(0xffffffffu, q, o);
        }
        if (lane == 0) { sred[t][w] = s; qred[t][w] = q; }
    }
    __syncthreads();
    float g = gamma[d], be = beta[d];
#pragma unroll
    for (int t = 0; t < 12; t++) {
        float s = sred[t][0] + sred[t][1] + sred[t][2] + sred[t][3];
        float q = qred[t][0] + qred[t][1] + qred[t][2] + qred[t][3];
        float mu = s * (1.f / 128.f);
        float var = q * (1.f / 128.f) - mu * mu;
        v[t] = (v[t] - mu) * rsqrtf(var + 1e-5f) * g + be;
    }
    const float CT[12] = {1.f, 0.8660254037844386f, 0.5f, 0.f, -0.5f, -0.8660254037844386f,
                          -1.f, -0.8660254037844386f, -0.5f, 0.f, 0.5f, 0.8660254037844386f};
    const float ST[12] = {0.f, 0.5f, 0.8660254037844386f, 1.f, 0.8660254037844386f, 0.5f,
                          0.f, -0.5f, -0.8660254037844386f, -1.f, -0.8660254037844386f, -0.5f};
#pragma unroll
    for (int f = 0; f < 7; f++) {
        float sr = 0.f, si = 0.f;
#pragma unroll
        for (int t = 0; t < 12; t++) {
            int k = (f * t) % 12;
            sr += v[t] * CT[k];
            si -= v[t] * ST[k];
        }
        long long o = ((long long)(b * 7 + f)) * 262144 + n * 128 + d;
        bf16 h, l;
        split1(sr, h, l); Rh[o] = h; Rl[o] = l;
        split1(si, h, l); Ih[o] = h; Il[o] = l;
    }
}

__global__ void irfft12(const float* __restrict__ HR, const float* __restrict__ HI,
                        const float* __restrict__ x, float* __restrict__ out)
{
    int idx = blockIdx.x * 256 + threadIdx.x;
    int b = idx >> 18, nd = idx & 262143;
    float hr[7], hi[7];
#pragma unroll
    for (int f = 0; f < 7; f++) {
        long long o = ((long long)b * 7 + f) * 262144 + nd;
        hr[f] = HR[o]; hi[f] = HI[o];
    }
    const float CT[12] = {1.f, 0.8660254037844386f, 0.5f, 0.f, -0.5f, -0.8660254037844386f,
                          -1.f, -0.8660254037844386f, -0.5f, 0.f, 0.5f, 0.8660254037844386f};
    const float ST[12] = {0.f, 0.5f, 0.8660254037844386f, 1.f, 0.8660254037844386f, 0.5f,
                          0.f, -0.5f, -0.8660254037844386f, -1.f, -0.8660254037844386f, -0.5f};
#pragma unroll
    for (int t = 0; t < 12; t++) {
        float acc = hr[0] + ((t & 1) ? -hr[6] : hr[6]);
#pragma unroll
        for (int f = 1; f < 6; f++) {
            int k = (f * t) % 12;
            acc += 2.f * (hr[f] * CT[k] - hi[f] * ST[k]);
        }
        long long o = ((long long)b * 12 + t) * 262144 + nd;
        out[o] = x[o] + acc * (1.f / 12.f);
    }
}

extern "C" void kernel_launch(void* const* d_in, const int* in_sizes, int n_in,
                              void* d_out, int out_size)
{
    const float* x   = (const float*)d_in[0];
    const float* Wd1 = (const float*)d_in[1];  const float* bd1 = (const float*)d_in[2];
    const float* Wd2 = (const float*)d_in[3];  const float* bd2 = (const float*)d_in[4];
    const float* Wq  = (const float*)d_in[5];  const float* bq  = (const float*)d_in[6];
    const float* Wk  = (const float*)d_in[7];  const float* bk  = (const float*)d_in[8];
    const float* Wv  = (const float*)d_in[9];  const float* bv  = (const float*)d_in[10];
    const float* Wu1 = (const float*)d_in[11]; const float* bu1 = (const float*)d_in[12];
    const float* Wu2 = (const float*)d_in[13]; const float* bu2 = (const float*)d_in[14];
    const float* gamma = (const float*)d_in[15];
    const float* beta  = (const float*)d_in[16];
    const float* Wr1 = (const float*)d_in[17]; const float* br1 = (const float*)d_in[18];
    const float* Wr2 = (const float*)d_in[19]; const float* br2 = (const float*)d_in[20];
    const float* Wi1 = (const float*)d_in[21]; const float* bi1 = (const float*)d_in[22];
    const float* Wi2 = (const float*)d_in[23]; const float* bi2 = (const float*)d_in[24];
    float* out = (float*)d_out;

    float* A = nullptr;
    cudaGetSymbolAddress((void**)&A, g_arena);

    float* S   = A + OFF_S;
    bf16* Uh   = (bf16*)(A + OFF_S);
    bf16* Sh   = (bf16*)(A + OFF_SP);   bf16* Sl = Sh + 67108864LL;
    float* ON  = A + OFF_SP;
    bf16* H1h  = (bf16*)(A + OFF_H1P);
    bf16* QKVh = (bf16*)(A + OFF_QKVP); bf16* QKVl = QKVh + 12582912LL;
    bf16* VTh  = (bf16*)(A + OFF_VTP);  bf16* VTl = VTh + 4194304LL;
    bf16* Oh   = (bf16*)(A + OFF_OP);
    bf16* Rh   = (bf16*)(A + OFF_REP);  bf16* Rl = Rh + 29360128LL;
    bf16* Ih   = (bf16*)(A + OFF_IMP);  bf16* Il = Ih + 29360128LL;
    bf16* H2h  = (bf16*)(A + OFF_H2P);
    float* HR  = A + OFF_REP;
    float* HI  = A + OFF_IMP;
    bf16* WQKVh = (bf16*)(A + OFF_WQKVP); float* BQKV = A + OFF_BQKV;
    bf16* WU1h  = (bf16*)(A + OFF_WU1P);
    bf16* WU2h  = (bf16*)(A + OFF_WU2P);
    bf16* W1Ah  = (bf16*)(A + OFF_W1AP);  bf16* W1Bh = (bf16*)(A + OFF_W1BP);
    float* B1A  = A + OFF_B1A;            float* B1B = A + OFF_B1B;
    bf16* WCRh  = (bf16*)(A + OFF_WCRP);  bf16* WCIh = (bf16*)(A + OFF_WCIP);
    float* BCR  = A + OFF_BCR;            float* BCI = A + OFF_BCI;

    cudaFuncSetAttribute(gemm_pl, cudaFuncAttributeMaxDynamicSharedMemorySize, 98304);
    cudaFuncSetAttribute(gemm_f32, cudaFuncAttributeMaxDynamicSharedMemorySize, 65536);

    // weight prep
    wqkv_fold<<<384, 128>>>(Wq, bq, Wk, bk, Wv, bv, Wd2, bd2, WQKVh, BQKV);
    build_w1<<<128, 256>>>(Wr1, br1, Wi1, bi1, W1Ah, B1A, W1Bh, B1B);
    build_wcat<<<128, 256>>>(Wr2, br2, Wi2, bi2, WCRh, BCR, WCIh, BCI);
    wconv<<<768, 256>>>(Wu1, WU1h, 196608, 196608);
    wconv<<<9216, 256>>>(Wu2, WU2h, 2359296, 2359296);

    // conv_down G1 (x gather, f32 in) -> H1 planes
    gemm_f32<<<dim3(1, 256, 1), 256, 65536>>>(x, Wd1, bd1, (void*)H1h,
        1536, 1536, 128, 128, 1.f, 1, 1, 4194304LL);
    // QKV (folded) -> QKV planes
    gemm_pl<<<dim3(3, 256, 1), 256, 98304>>>(H1h, WQKVh, BQKV, (void*)QKVh,
        128, 128, 128, 384, 128, 1.f, 0, 1, 4194304LL, 49152LL, 12582912LL, 0, 0, 0);
    // QK^T -> S f32
    gemm_pl<<<dim3(16, 16, 16), 256, 98304>>>(QKVh, QKVh + 128, nullptr, (void*)S,
        128, 384, 384, 2048, 128, 0.125f, 0, 0, 12582912LL, 12582912LL, 0,
        786432LL, 786432LL, 4194304LL);
    softmax2048<<<32768, 256>>>(S, Sh, Sl);
    transpose_v<<<dim3(64, 4, 16), 256>>>(QKVh, QKVl, VTh, VTl);
    // S@V -> O planes
    gemm_pl<<<dim3(1, 16, 16), 256, 98304>>>(Sh, VTh, nullptr, (void*)Oh,
        2048, 2048, 2048, 128, 128, 1.f, 0, 1, 67108864LL, 4194304LL, 4194304LL,
        4194304LL, 262144LL, 262144LL);
    // conv_up
    gemm_pl<<<dim3(12, 256, 1), 256, 98304>>>(Oh, WU1h, bu1, (void*)Uh,
        128, 128, 128, 1536, 128, 1.f, 1, 1, 4194304LL, 196608LL, 50331648LL, 0, 0, 0);
    gemm_pl<<<dim3(12, 256, 1), 256, 98304>>>(Uh, WU2h, bu2, (void*)ON,
        1536, 1536, 1536, 1536, 128, 1.f, 0, 0, 50331648LL, 2359296LL, 0, 0, 0, 0);
    // residual + LN + rfft -> RE/IM planes
    ln_dft<<<32768, 128>>>(ON, x, gamma, beta, Rh, Rl, Ih, Il);
    // FFT MLP layer 1 (gelu) -> H2 planes
    gemm_pl<<<dim3(2, 1792, 1), 256, 98304>>>(Rh, W1Ah, B1A, (void*)H2h,
        128, 128, 128, 512, 256, 1.f, 2, 1, 29360128LL, 32768LL, 117440512LL, 0, 0, 0);
    gemm_pl<<<dim3(2, 1792, 1), 256, 98304>>>(Ih, W1Bh, B1B, (void*)(H2h + 128),
        128, 128, 128, 512, 256, 1.f, 2, 1, 29360128LL, 32768LL, 117440512LL, 0, 0, 0);
    // FFT MLP layer 2 -> HR/HI f32
    gemm_pl<<<dim3(1, 1792, 1), 256, 98304>>>(H2h, WCRh, BCR, (void*)HR,
        256, 512, 256, 128, 128, 1.f, 0, 0, 117440512LL, 32768LL, 0, 0, 0, 0);
    gemm_pl<<<dim3(1, 1792, 1), 256, 98304>>>(H2h + 256, WCIh, BCI, (void*)HI,
        256, 512, 256, 128, 128, 1.f, 0, 0, 117440512LL, 32768LL, 0, 0, 0, 0);
    // irfft + residual
    irfft12<<<16384, 256>>>(HR, HI, x, out);
}

// round 17
// speedup vs baseline: 1.0576x; 1.0576x over previous
#include <cuda_runtime.h>
#include <cuda_fp16.h>
#include <stdint.h>
#include <math.h>

// NOTE: "bf16" is now __half (fp16). Name kept to minimize diff vs validated r12 kernel.
typedef __half bf16;

// B=16,T=12,N=2048,D=128. Arena offsets (float units). Planes: hi then lo (fp16).
static const long long OFF_S   = 0;            // S f32 67108864 ; then Up planes
static const long long OFF_SP  = 67108864LL;   // SP planes ; then ON f32
static const long long OFF_H1P = 134217728LL;
static const long long OFF_QKVP= 138412032LL;
static const long long OFF_VTP = 150994944LL;
static const long long OFF_OP  = 155189248LL;
static const long long OFF_REP = 159383552LL;  // later HR f32
static const long long OFF_IMP = 188743680LL;  // later HI f32
static const long long OFF_H2P = 218103808LL;  // 117440512
static const long long OFF_WQKVP=335544320LL;
static const long long OFF_BQKV =335593472LL;
static const long long OFF_WU1P =335593856LL;
static const long long OFF_WU2P =335790464LL;
static const long long OFF_W1AP =338149760LL;
static const long long OFF_W1BP =338182528LL;
static const long long OFF_B1A  =338215296LL;
static const long long OFF_B1B  =338215552LL;
static const long long OFF_WCRP =338215808LL;
static const long long OFF_WCIP =338248576LL;
static const long long OFF_BCR  =338281344LL;
static const long long OFF_BCI  =338281472LL;

__device__ float g_arena[338282496];

__device__ __forceinline__ float epi_f(float v, int epi) {
    if (epi == 1) return v > 0.f ? v : 0.f;
    if (epi == 2) return 0.5f * v * (1.f + erff(v * 0.7071067811865476f));
    return v;
}
__device__ __forceinline__ void split1(float a, bf16& h, bf16& l) {
    h = __float2half_rn(a);
    l = __float2half_rn(a - __half2float(h));
}
__device__ __forceinline__ void split2(float a, float b, uint32_t& h, uint32_t& l) {
    bf16 ha, la, hb, lb;
    split1(a, ha, la); split1(b, hb, lb);
    h = (uint32_t)__half_as_ushort(ha) | ((uint32_t)__half_as_ushort(hb) << 16);
    l = (uint32_t)__half_as_ushort(la) | ((uint32_t)__half_as_ushort(lb) << 16);
}
__device__ __forceinline__ void ldsm4(uint32_t &r0, uint32_t &r1, uint32_t &r2, uint32_t &r3,
                                      uint32_t addr) {
    asm volatile("ldmatrix.sync.aligned.m8n8.x4.shared.b16 {%0,%1,%2,%3}, [%4];"
                 : "=r"(r0), "=r"(r1), "=r"(r2), "=r"(r3) : "r"(addr));
}
__device__ __forceinline__ void mma_bf16(float* d, const uint32_t* a, const uint32_t* b) {
    asm volatile("mma.sync.aligned.m16n8k16.row.col.f32.f16.f16.f32 "
                 "{%0,%1,%2,%3}, {%4,%5,%6,%7}, {%8,%9}, {%0,%1,%2,%3};"
                 : "+f"(d[0]), "+f"(d[1]), "+f"(d[2]), "+f"(d[3])
                 : "r"(a[0]), "r"(a[1]), "r"(a[2]), "r"(a[3]), "r"(b[0]), "r"(b[1]));
}
__device__ __forceinline__ void cpa16(uint32_t dst, const void* src) {
    asm volatile("cp.async.cg.shared.global [%0], [%1], 16;" :: "r"(dst), "l"(src));
}
__device__ __forceinline__ void split_pack(float4 v0, float4 v1, uint4 &hi, uint4 &lo) {
    float f[8] = {v0.x, v0.y, v0.z, v0.w, v1.x, v1.y, v1.z, v1.w};
    uint32_t h[4], l[4];
#pragma unroll
    for (int i = 0; i < 4; i++) split2(f[2*i], f[2*i+1], h[i], l[i]);
    hi = make_uint4(h[0], h[1], h[2], h[3]);
    lo = make_uint4(l[0], l[1], l[2], l[3]);
}
__device__ __forceinline__ const float* xgather_ptr(const float* X, int row, int k) {
    int t = k >> 7, d = k & 127, b = row >> 11, n = row & 2047;
    return X + ((long long)(b * 12 + t) * 2048 + n) * 128 + d;
}

// shared epilogue writer
__device__ __forceinline__ void epi_store(void* Cv, const float* bias, float acc[4][4][4],
    int bx, int by, long long bzsC, int ldc, int colstep, long long pC,
    float alpha, int epi, int omode, int t)
{
    const int lane = t & 31;
    const int wm = (t >> 7) * 64, wn = ((t >> 5) & 3) * 32;
    const int g = lane >> 2, tt = lane & 3;
    const long long rowBase = (long long)by * 128 + wm + g;
#pragma unroll
    for (int mf = 0; mf < 4; mf++) {
#pragma unroll
        for (int nf = 0; nf < 4; nf++) {
            const int nIdx = bx * 128 + wn + nf * 8 + 2 * tt;
            const int col = bx * colstep + wn + nf * 8 + 2 * tt;
            float2 bv = make_float2(0.f, 0.f);
            if (bias) bv = *(const float2*)(bias + nIdx);
            float x0 = epi_f(acc[mf][nf][0] * alpha + bv.x, epi);
            float y0 = epi_f(acc[mf][nf][1] * alpha + bv.y, epi);
            float x1 = epi_f(acc[mf][nf][2] * alpha + bv.x, epi);
            float y1 = epi_f(acc[mf][nf][3] * alpha + bv.y, epi);
            const long long r0 = (rowBase + mf * 16) * ldc + col;
            if (omode == 0) {
                float* C = (float*)Cv + bzsC;
                *(float2*)(C + r0) = make_float2(x0, y0);
                *(float2*)(C + r0 + 8LL * ldc) = make_float2(x1, y1);
            } else {
                bf16* Ch = (bf16*)Cv + bzsC;
                bf16* Cl = Ch + pC;
                uint32_t h, l;
                split2(x0, y0, h, l);
                *(uint32_t*)(Ch + r0) = h; *(uint32_t*)(Cl + r0) = l;
                split2(x1, y1, h, l);
                *(uint32_t*)(Ch + r0 + 8LL * ldc) = h; *(uint32_t*)(Cl + r0 + 8LL * ldc) = l;
            }
        }
    }
}

// ===== plane-input GEMM, 2-stage cp.async pipeline =====
// terms==3: acc += ah*bh + al*bh + ah*bl  (A,B both hi/lo planes)
// terms==2: acc += ah*bh + al*bh          (B hi plane only; lo never loaded)
__global__ void __launch_bounds__(256, 2)
gemm_pl(const bf16* __restrict__ Ah, const bf16* __restrict__ Bh,
        const float* __restrict__ bias, void* __restrict__ Cv,
        int K, int lda, int ldb, int ldc, int colstep, float alpha, int epi, int omode,
        int terms,
        long long pA, long long pB, long long pC,
        long long sA, long long sB, long long sC)
{
    extern __shared__ __align__(16) char smc[];
    const int t = threadIdx.x;
    const int bx = blockIdx.x, by = blockIdx.y, bz = blockIdx.z;
    const int lane = t & 31;
    const uint32_t smemBase = (uint32_t)__cvta_generic_to_shared(smc);

    const int lr2 = t >> 1, hf = t & 1, s7b = lr2 & 7;
    const bf16* Agh = Ah + bz * sA + (long long)(by * 128 + lr2) * lda;
    const bf16* Agl = Agh + pA;
    const bf16* Bgh = Bh + bz * sB + (long long)(bx * 128 + lr2) * ldb;
    const bf16* Bgl = Bgh + pB;
    const uint32_t rowb = smemBase + (uint32_t)lr2 * 128;

    const int sub = lane >> 3, l7 = lane & 7;
    const int wm = (t >> 7) * 64, wn = ((t >> 5) & 3) * 32;
    const int aRowOff = wm + l7 + ((sub & 1) << 3);
    const int aSel = sub >> 1;
    const int bRowOff = wn + l7 + ((sub >> 1) << 3);
    const int bSel = sub & 1;

    float acc[4][4][4];
#pragma unroll
    for (int i = 0; i < 4; i++)
#pragma unroll
        for (int j = 0; j < 4; j++)
#pragma unroll
            for (int q = 0; q < 4; q++) acc[i][j][q] = 0.f;

    const int nk = K >> 5;
#define ISSUE(S) do { \
    const uint32_t sb = rowb + (uint32_t)((S) & 1) * 32768u; \
    const int k0 = (S) * 32; \
    _Pragma("unroll") \
    for (int j = 0; j < 2; j++) { \
        int u = hf * 2 + j; \
        cpa16(sb + (uint32_t)((u ^ s7b) << 4), Agh + k0 + u * 8); \
        cpa16(sb + (uint32_t)(((u + 4) ^ s7b) << 4), Agl + k0 + u * 8); \
        cpa16(sb + 16384u + (uint32_t)((u ^ s7b) << 4), Bgh + k0 + u * 8); \
        if (terms == 3) \
            cpa16(sb + 16384u + (uint32_t)(((u + 4) ^ s7b) << 4), Bgl + k0 + u * 8); \
    } \
    asm volatile("cp.async.commit_group;"); \
} while (0)

    ISSUE(0);
    for (int s = 0; s < nk; s++) {
        const bool more = (s + 1) < nk;
        if (more) ISSUE(s + 1);
        if (more) asm volatile("cp.async.wait_group 1;");
        else      asm volatile("cp.async.wait_group 0;");
        __syncthreads();
        const uint32_t stg = smemBase + (uint32_t)(s & 1) * 32768u;
#pragma unroll
        for (int kh = 0; kh < 2; kh++) {
            uint32_t ah[4][4], al[4][4], bh[4][2], bl[4][2];
#pragma unroll
            for (int mf = 0; mf < 4; mf++) {
                const uint32_t rb = stg + (uint32_t)(aRowOff + mf * 16) * 128;
                const int u0 = 2 * kh + aSel;
                ldsm4(ah[mf][0], ah[mf][1], ah[mf][2], ah[mf][3], rb + ((u0 ^ l7) << 4));
                ldsm4(al[mf][0], al[mf][1], al[mf][2], al[mf][3], rb + (((u0 + 4) ^ l7) << 4));
            }
#pragma unroll
            for (int np = 0; np < 2; np++) {
                const uint32_t rb = stg + 16384 + (uint32_t)(bRowOff + np * 16) * 128;
                const int u0 = 2 * kh + bSel;
                uint32_t r0, r1, r2, r3;
                ldsm4(r0, r1, r2, r3, rb + ((u0 ^ l7) << 4));
                bh[np*2][0] = r0; bh[np*2][1] = r1; bh[np*2+1][0] = r2; bh[np*2+1][1] = r3;
                if (terms == 3) {
                    ldsm4(r0, r1, r2, r3, rb + (((u0 + 4) ^ l7) << 4));
                    bl[np*2][0] = r0; bl[np*2][1] = r1; bl[np*2+1][0] = r2; bl[np*2+1][1] = r3;
                }
            }
#pragma unroll
            for (int mf = 0; mf < 4; mf++)
#pragma unroll
                for (int nf = 0; nf < 4; nf++) {
                    mma_bf16(acc[mf][nf], ah[mf], bh[nf]);
                    mma_bf16(acc[mf][nf], al[mf], bh[nf]);
                    if (terms == 3) mma_bf16(acc[mf][nf], ah[mf], bl[nf]);
                }
        }
        __syncthreads();
    }
#undef ISSUE
    epi_store(Cv, bias, acc, bx, by, (long long)bz * sC, ldc, colstep, pC, alpha, epi, omode, t);
}

// ===== f32-input GEMM (x-gather); used only for conv_down G1; 3-term fp16 =====
__global__ void __launch_bounds__(256)
gemm_f32(const float* __restrict__ A, const float* __restrict__ B,
         const float* __restrict__ bias, void* __restrict__ Cv,
         int K, int ldb, int ldc, int colstep, float alpha, int epi, int omode, long long pC)
{
    extern __shared__ __align__(16) uint4 sm[];
    const int t = threadIdx.x;
    const int bx = blockIdx.x, by = blockIdx.y;
    const int lane = t & 31;

    const int lr = t >> 2, lc = t & 3, s7 = lr & 7;
    const float* Bg0 = B + (long long)(bx * 128 + lr) * ldb + lc * 8;
    const float* Bg1 = Bg0 + (long long)64 * ldb;

    const int sub = lane >> 3, l7 = lane & 7;
    const int wm = (t >> 7) * 64, wn = ((t >> 5) & 3) * 32;
    const int aRowOff = wm + l7 + ((sub & 1) << 3);
    const int aSel = sub >> 1;
    const int bRowOff = wn + l7 + ((sub >> 1) << 3);
    const int bSel = sub & 1;
    const uint32_t smemBase = (uint32_t)__cvta_generic_to_shared(sm);

    float acc[4][4][4];
#pragma unroll
    for (int i = 0; i < 4; i++)
#pragma unroll
        for (int j = 0; j < 4; j++)
#pragma unroll
            for (int q = 0; q < 4; q++) acc[i][j][q] = 0.f;

    const int nk = K >> 5;
    {
        const float* pa0 = xgather_ptr(A, by*128 + lr, lc*8);
        const float* pa1 = xgather_ptr(A, by*128 + lr + 64, lc*8);
        uint4 hi, lo;
        uint4* bA0 = sm + lr * 8;        uint4* bA1 = bA0 + 512;
        uint4* bB0 = sm + 1024 + lr * 8; uint4* bB1 = bB0 + 512;
        split_pack(*(const float4*)pa0, *(const float4*)(pa0+4), hi, lo);
        bA0[lc ^ s7] = hi; bA0[(lc+4) ^ s7] = lo;
        split_pack(*(const float4*)pa1, *(const float4*)(pa1+4), hi, lo);
        bA1[lc ^ s7] = hi; bA1[(lc+4) ^ s7] = lo;
        split_pack(*(const float4*)Bg0, *(const float4*)(Bg0+4), hi, lo);
        bB0[lc ^ s7] = hi; bB0[(lc+4) ^ s7] = lo;
        split_pack(*(const float4*)Bg1, *(const float4*)(Bg1+4), hi, lo);
        bB1[lc ^ s7] = hi; bB1[(lc+4) ^ s7] = lo;
    }
    __syncthreads();

    for (int s = 0; s < nk; s++) {
        float4 a00, a01, a10, a11, b00, b01, b10, b11;
        const bool more = (s + 1) < nk;
        if (more) {
            const float* pa0 = xgather_ptr(A, by*128 + lr, (s+1)*32 + lc*8);
            const float* pa1 = xgather_ptr(A, by*128 + lr + 64, (s+1)*32 + lc*8);
            const float* pb0 = Bg0 + (s+1)*32; const float* pb1 = Bg1 + (s+1)*32;
            a00 = *(const float4*)pa0; a01 = *(const float4*)(pa0+4);
            a10 = *(const float4*)pa1; a11 = *(const float4*)(pa1+4);
            b00 = *(const float4*)pb0; b01 = *(const float4*)(pb0+4);
            b10 = *(const float4*)pb1; b11 = *(const float4*)(pb1+4);
        }
        const uint32_t stg = smemBase + (uint32_t)(s & 1) * 32768u;
#pragma unroll
        for (int kh = 0; kh < 2; kh++) {
            uint32_t ah[4][4], al[4][4], bh[4][2], bl[4][2];
#pragma unroll
            for (int mf = 0; mf < 4; mf++) {
                const uint32_t rb = stg + (uint32_t)(aRowOff + mf * 16) * 128;
                const int u0 = 2 * kh + aSel;
                ldsm4(ah[mf][0], ah[mf][1], ah[mf][2], ah[mf][3], rb + ((u0 ^ l7) << 4));
                ldsm4(al[mf][0], al[mf][1], al[mf][2], al[mf][3], rb + (((u0 + 4) ^ l7) << 4));
            }
#pragma unroll
            for (int np = 0; np < 2; np++) {
                const uint32_t rb = stg + 16384 + (uint32_t)(bRowOff + np * 16) * 128;
                const int u0 = 2 * kh + bSel;
                uint32_t r0, r1, r2, r3;
                ldsm4(r0, r1, r2, r3, rb + ((u0 ^ l7) << 4));
                bh[np*2][0] = r0; bh[np*2][1] = r1; bh[np*2+1][0] = r2; bh[np*2+1][1] = r3;
                ldsm4(r0, r1, r2, r3, rb + (((u0 + 4) ^ l7) << 4));
                bl[np*2][0] = r0; bl[np*2][1] = r1; bl[np*2+1][0] = r2; bl[np*2+1][1] = r3;
            }
#pragma unroll
            for (int mf = 0; mf < 4; mf++)
#pragma unroll
                for (int nf = 0; nf < 4; nf++) {
                    mma_bf16(acc[mf][nf], ah[mf], bh[nf]);
                    mma_bf16(acc[mf][nf], ah[mf], bl[nf]);
                    mma_bf16(acc[mf][nf], al[mf], bh[nf]);
                }
        }
        if (more) {
            const uint32_t ns = (uint32_t)((s + 1) & 1);
            uint4 hi, lo;
            uint4* bA0 = sm + ns*2048 + lr * 8;        uint4* bA1 = bA0 + 512;
            uint4* bB0 = sm + ns*2048 + 1024 + lr * 8; uint4* bB1 = bB0 + 512;
            split_pack(a00, a01, hi, lo); bA0[lc ^ s7] = hi; bA0[(lc+4) ^ s7] = lo;
            split_pack(a10, a11, hi, lo); bA1[lc ^ s7] = hi; bA1[(lc+4) ^ s7] = lo;
            split_pack(b00, b01, hi, lo); bB0[lc ^ s7] = hi; bB0[(lc+4) ^ s7] = lo;
            split_pack(b10, b11, hi, lo); bB1[lc ^ s7] = hi; bB1[(lc+4) ^ s7] = lo;
        }
        __syncthreads();
    }
    epi_store(Cv, bias, acc, bx, by, 0, ldc, colstep, pC, alpha, epi, omode, t);
}

// ===== producers / prep =====
__global__ void wqkv_fold(const float* __restrict__ Wq, const float* __restrict__ bq,
                          const float* __restrict__ Wk, const float* __restrict__ bk,
                          const float* __restrict__ Wv, const float* __restrict__ bv,
                          const float* __restrict__ Wd2, const float* __restrict__ bd2,
                          bf16* __restrict__ Wh, float* __restrict__ BQKV)
{
    int i = blockIdx.x, j = threadIdx.x;
    const float* row = (i < 128) ? Wq + i * 128 : (i < 256) ? Wk + (i - 128) * 128 : Wv + (i - 256) * 128;
    float bo = (i < 128) ? bq[i] : (i < 256) ? bk[i - 128] : bv[i - 256];
    float acc = 0.f, accb = 0.f;
    for (int c = 0; c < 128; c++) {
        float w = row[c];
        acc += w * Wd2[c * 128 + j];
        accb += w * bd2[c];
    }
    bf16 h, l; split1(acc, h, l);
    Wh[i * 128 + j] = h; Wh[49152 + i * 128 + j] = l;
    if (j == 0) BQKV[i] = accb + bo;
}

__global__ void build_w1(const float* __restrict__ Wr1, const float* __restrict__ br1,
                         const float* __restrict__ Wi1, const float* __restrict__ bi1,
                         bf16* __restrict__ W1A, float* __restrict__ b1a,
                         bf16* __restrict__ W1B, float* __restrict__ b1b)
{
    int i = blockIdx.x * 256 + threadIdx.x;
    int r = i >> 7, c = i & 127;
    float va = (r < 128) ? Wr1[r * 128 + c] : Wi1[(r - 128) * 128 + c];
    float vb = (r < 128) ? Wi1[r * 128 + c] : Wr1[(r - 128) * 128 + c];
    bf16 h, l;
    split1(va, h, l); W1A[i] = h; W1A[32768 + i] = l;
    split1(vb, h, l); W1B[i] = h; W1B[32768 + i] = l;
    if (i < 256) {
        b1a[i] = (i < 128) ? br1[i] : bi1[i - 128];
        b1b[i] = (i < 128) ? bi1[i] : br1[i - 128];
    }
}

__global__ void build_wcat(const float* __restrict__ Wr2, const float* __restrict__ br2,
                           const float* __restrict__ Wi2, const float* __restrict__ bi2,
                           bf16* __restrict__ WCR, float* __restrict__ bcr,
                           bf16* __restrict__ WCI, float* __restrict__ bci)
{
    int i = blockIdx.x * 256 + threadIdx.x;
    int n = i >> 8, k = i & 255;
    float vr, vi;
    if (k < 128) { vr = Wr2[n * 128 + k];        vi = Wi2[n * 128 + k]; }
    else         { vr = -Wi2[n * 128 + k - 128]; vi = Wr2[n * 128 + k - 128]; }
    bf16 h, l;
    split1(vr, h, l); WCR[i] = h; WCR[32768 + i] = l;
    split1(vi, h, l); WCI[i] = h; WCI[32768 + i] = l;
    if (i < 128) { bcr[i] = br2[i] - bi2[i]; bci[i] = bi2[i] + br2[i]; }
}

__global__ void wconv(const float* __restrict__ W, bf16* __restrict__ Wp, int n, int plane) {
    int i = blockIdx.x * 256 + threadIdx.x;
    if (i < n) { bf16 h, l; split1(W[i], h, l); Wp[i] = h; Wp[plane + i] = l; }
}

__global__ void transpose_v(const bf16* __restrict__ Qh, const bf16* __restrict__ Ql,
                            bf16* __restrict__ VTh, bf16* __restrict__ VTl)
{
    __shared__ uint32_t tile[32][33];
    int b = blockIdx.z, n0 = blockIdx.x * 32, d0 = blockIdx.y * 32;
    int tx = threadIdx.x & 31, ty = threadIdx.x >> 5;
#pragma unroll
    for (int i = 0; i < 32; i += 8) {
        long long idx = ((long long)b * 2048 + n0 + ty + i) * 384 + 256 + d0 + tx;
        tile[ty + i][tx] = (uint32_t)__half_as_ushort(Qh[idx])
                         | ((uint32_t)__half_as_ushort(Ql[idx]) << 16);
    }
    __syncthreads();
#pragma unroll
    for (int i = 0; i < 32; i += 8) {
        uint32_t p = tile[tx][ty + i];
        long long o = (long long)b * 262144 + (long long)(d0 + ty + i) * 2048 + n0 + tx;
        VTh[o] = __ushort_as_half((unsigned short)(p & 0xffff));
        VTl[o] = __ushort_as_half((unsigned short)(p >> 16));
    }
}

__global__ void softmax2048(const float* __restrict__ S, bf16* __restrict__ Sh, bf16* __restrict__ Sl) {
    const float* row = S + (long long)blockIdx.x * 2048;
    long long obase = (long long)blockIdx.x * 2048;
    int t = threadIdx.x;
    float v[8], mx = -3.4e38f;
#pragma unroll
    for (int i = 0; i < 8; i++) { v[i] = row[t + (i << 8)]; mx = fmaxf(mx, v[i]); }
    __shared__ float red[8];
#pragma unroll
    for (int o = 16; o; o >>= 1) mx = fmaxf(mx, __shfl_xor_sync(0xffffffffu, mx, o));
    if ((t & 31) == 0) red[t >> 5] = mx;
    __syncthreads();
    mx = red[0];
#pragma unroll
    for (int i = 1; i < 8; i++) mx = fmaxf(mx, red[i]);
    float s = 0.f;
#pragma unroll
    for (int i = 0; i < 8; i++) { v[i] = __expf(v[i] - mx); s += v[i]; }
#pragma unroll
    for (int o = 16; o; o >>= 1) s += __shfl_xor_sync(0xffffffffu, s, o);
    __syncthreads();
    if ((t & 31) == 0) red[t >> 5] = s;
    __syncthreads();
    s = 0.f;
#pragma unroll
    for (int i = 0; i < 8; i++) s += red[i];
    float inv = 1.f / s;
#pragma unroll
    for (int i = 0; i < 8; i++) {
        bf16 h, l; split1(v[i] * inv, h, l);
        Sh[obase + t + (i << 8)] = h; Sl[obase + t + (i << 8)] = l;
    }
}

__global__ void ln_dft(const float* __restrict__ ON, const float* __restrict__ x,
                       const float* __restrict__ gamma, const float* __restrict__ beta,
                       bf16* __restrict__ Rh, bf16* __restrict__ Rl,
                       bf16* __restrict__ Ih, bf16* __restrict__ Il)
{
    int bn = blockIdx.x;
    int d = threadIdx.x;
    int b = bn >> 11, n = bn & 2047;
    float v[12];
    const float* onp = ON + (long long)bn * 1536 + d;
    const float* xp = x + ((long long)(b * 12) * 2048 + n) * 128 + d;
#pragma unroll
    for (int t = 0; t < 12; t++) v[t] = onp[t * 128] + xp[(long long)t * 262144];

    __shared__ float sred[12][4], qred[12][4];
    int w = d >> 5, lane = d & 31;
#pragma unroll
    for (int t = 0; t < 12; t++) {
        float s = v[t], q = v[t] * v[t];
#pragma unroll
        for (int o = 16; o; o >>= 1) {
            s += __shfl_xor_sync(0xffffffffu, s, o);
            q += __shfl_xor_sync(0xffffffffu, q, o);
        }
        if (lane == 0) { sred[t][w] = s; qred[t][w] = q; }
    }
    __syncthreads();
    float g = gamma[d], be = beta[d];
#pragma unroll
    for (int t = 0; t < 12; t++) {
        float s = sred[t][0] + sred[t][1] + sred[t][2] + sred[t][3];
        float q = qred[t][0] + qred[t][1] + qred[t][2] + qred[t][3];
        float mu = s * (1.f / 128.f);
        float var = q * (1.f / 128.f) - mu * mu;
        v[t] = (v[t] - mu) * rsqrtf(var + 1e-5f) * g + be;
    }
    const float CT[12] = {1.f, 0.8660254037844386f, 0.5f, 0.f, -0.5f, -0.8660254037844386f,
                          -1.f, -0.8660254037844386f, -0.5f, 0.f, 0.5f, 0.8660254037844386f};
    const float ST[12] = {0.f, 0.5f, 0.8660254037844386f, 1.f, 0.8660254037844386f, 0.5f,
                          0.f, -0.5f, -0.8660254037844386f, -1.f, -0.8660254037844386f, -0.5f};
#pragma unroll
    for (int f = 0; f < 7; f++) {
        float sr = 0.f, si = 0.f;
#pragma unroll
        for (int t = 0; t < 12; t++) {
            int k = (f * t) % 12;
            sr += v[t] * CT[k];
            si -= v[t] * ST[k];
        }
        long long o = ((long long)(b * 7 + f)) * 262144 + n * 128 + d;
        bf16 h, l;
        split1(sr, h, l); Rh[o] = h; Rl[o] = l;
        split1(si, h, l); Ih[o] = h; Il[o] = l;
    }
}

__global__ void irfft12(const float* __restrict__ HR, const float* __restrict__ HI,
                        const float* __restrict__ x, float* __restrict__ out)
{
    int idx = blockIdx.x * 256 + threadIdx.x;
    int b = idx >> 18, nd = idx & 262143;
    float hr[7], hi[7];
#pragma unroll
    for (int f = 0; f < 7; f++) {
        long long o = ((long long)b * 7 + f) * 262144 + nd;
        hr[f] = HR[o]; hi[f] = HI[o];
    }
    const float CT[12] = {1.f, 0.8660254037844386f, 0.5f, 0.f, -0.5f, -0.8660254037844386f,
                          -1.f, -0.8660254037844386f, -0.5f, 0.f, 0.5f, 0.8660254037844386f};
    const float ST[12] = {0.f, 0.5f, 0.8660254037844386f, 1.f, 0.8660254037844386f, 0.5f,
                          0.f, -0.5f, -0.8660254037844386f, -1.f, -0.8660254037844386f, -0.5f};
#pragma unroll
    for (int t = 0; t < 12; t++) {
        float acc = hr[0] + ((t & 1) ? -hr[6] : hr[6]);
#pragma unroll
        for (int f = 1; f < 6; f++) {
            int k = (f * t) % 12;
            acc += 2.f * (hr[f] * CT[k] - hi[f] * ST[k]);
        }
        long long o = ((long long)b * 12 + t) * 262144 + nd;
        out[o] = x[o] + acc * (1.f / 12.f);
    }
}

extern "C" void kernel_launch(void* const* d_in, const int* in_sizes, int n_in,
                              void* d_out, int out_size)
{
    const float* x   = (const float*)d_in[0];
    const float* Wd1 = (const float*)d_in[1];  const float* bd1 = (const float*)d_in[2];
    const float* Wd2 = (const float*)d_in[3];  const float* bd2 = (const float*)d_in[4];
    const float* Wq  = (const float*)d_in[5];  const float* bq  = (const float*)d_in[6];
    const float* Wk  = (const float*)d_in[7];  const float* bk  = (const float*)d_in[8];
    const float* Wv  = (const float*)d_in[9];  const float* bv  = (const float*)d_in[10];
    const float* Wu1 = (const float*)d_in[11]; const float* bu1 = (const float*)d_in[12];
    const float* Wu2 = (const float*)d_in[13]; const float* bu2 = (const float*)d_in[14];
    const float* gamma = (const float*)d_in[15];
    const float* beta  = (const float*)d_in[16];
    const float* Wr1 = (const float*)d_in[17]; const float* br1 = (const float*)d_in[18];
    const float* Wr2 = (const float*)d_in[19]; const float* br2 = (const float*)d_in[20];
    const float* Wi1 = (const float*)d_in[21]; const float* bi1 = (const float*)d_in[22];
    const float* Wi2 = (const float*)d_in[23]; const float* bi2 = (const float*)d_in[24];
    float* out = (float*)d_out;

    float* A = nullptr;
    cudaGetSymbolAddress((void**)&A, g_arena);

    float* S   = A + OFF_S;
    bf16* Uh   = (bf16*)(A + OFF_S);
    bf16* Sh   = (bf16*)(A + OFF_SP);   bf16* Sl = Sh + 67108864LL;
    float* ON  = A + OFF_SP;
    bf16* H1h  = (bf16*)(A + OFF_H1P);
    bf16* QKVh = (bf16*)(A + OFF_QKVP); bf16* QKVl = QKVh + 12582912LL;
    bf16* VTh  = (bf16*)(A + OFF_VTP);  bf16* VTl = VTh + 4194304LL;
    bf16* Oh   = (bf16*)(A + OFF_OP);
    bf16* Rh   = (bf16*)(A + OFF_REP);  bf16* Rl = Rh + 29360128LL;
    bf16* Ih   = (bf16*)(A + OFF_IMP);  bf16* Il = Ih + 29360128LL;
    bf16* H2h  = (bf16*)(A + OFF_H2P);
    float* HR  = A + OFF_REP;
    float* HI  = A + OFF_IMP;
    bf16* WQKVh = (bf16*)(A + OFF_WQKVP); float* BQKV = A + OFF_BQKV;
    bf16* WU1h  = (bf16*)(A + OFF_WU1P);
    bf16* WU2h  = (bf16*)(A + OFF_WU2P);
    bf16* W1Ah  = (bf16*)(A + OFF_W1AP);  bf16* W1Bh = (bf16*)(A + OFF_W1BP);
    float* B1A  = A + OFF_B1A;            float* B1B = A + OFF_B1B;
    bf16* WCRh  = (bf16*)(A + OFF_WCRP);  bf16* WCIh = (bf16*)(A + OFF_WCIP);
    float* BCR  = A + OFF_BCR;            float* BCI = A + OFF_BCI;

    cudaFuncSetAttribute(gemm_pl, cudaFuncAttributeMaxDynamicSharedMemorySize, 65536);
    cudaFuncSetAttribute(gemm_f32, cudaFuncAttributeMaxDynamicSharedMemorySize, 65536);

    // weight prep
    wqkv_fold<<<384, 128>>>(Wq, bq, Wk, bk, Wv, bv, Wd2, bd2, WQKVh, BQKV);
    build_w1<<<128, 256>>>(Wr1, br1, Wi1, bi1, W1Ah, B1A, W1Bh, B1B);
    build_wcat<<<128, 256>>>(Wr2, br2, Wi2, bi2, WCRh, BCR, WCIh, BCI);
    wconv<<<768, 256>>>(Wu1, WU1h, 196608, 196608);
    wconv<<<9216, 256>>>(Wu2, WU2h, 2359296, 2359296);

    // conv_down G1 (x gather, f32 in, 3-term) -> H1 planes
    gemm_f32<<<dim3(1, 256, 1), 256, 65536>>>(x, Wd1, bd1, (void*)H1h,
        1536, 1536, 128, 128, 1.f, 1, 1, 4194304LL);
    // QKV (folded, 3-term) -> QKV planes
    gemm_pl<<<dim3(3, 256, 1), 256, 65536>>>(H1h, WQKVh, BQKV, (void*)QKVh,
        128, 128, 128, 384, 128, 1.f, 0, 1, 3, 4194304LL, 49152LL, 12582912LL, 0, 0, 0);
    // QK^T (3-term) -> S f32
    gemm_pl<<<dim3(16, 16, 16), 256, 65536>>>(QKVh, QKVh + 128, nullptr, (void*)S,
        128, 384, 384, 2048, 128, 0.125f, 0, 0, 3, 12582912LL, 12582912LL, 0,
        786432LL, 786432LL, 4194304LL);
    softmax2048<<<32768, 256>>>(S, Sh, Sl);
    transpose_v<<<dim3(64, 4, 16), 256>>>(QKVh, QKVl, VTh, VTl);
    // S@V (3-term) -> O planes
    gemm_pl<<<dim3(1, 16, 16), 256, 65536>>>(Sh, VTh, nullptr, (void*)Oh,
        2048, 2048, 2048, 128, 128, 1.f, 0, 1, 3, 67108864LL, 4194304LL, 4194304LL,
        4194304LL, 262144LL, 262144LL);
    // conv_up (2-term: weight B)
    gemm_pl<<<dim3(12, 256, 1), 256, 65536>>>(Oh, WU1h, bu1, (void*)Uh,
        128, 128, 128, 1536, 128, 1.f, 1, 1, 2, 4194304LL, 196608LL, 50331648LL, 0, 0, 0);
    gemm_pl<<<dim3(12, 256, 1), 256, 65536>>>(Uh, WU2h, bu2, (void*)ON,
        1536, 1536, 1536, 1536, 128, 1.f, 0, 0, 2, 50331648LL, 2359296LL, 0, 0, 0, 0);
    // residual + LN + rfft -> RE/IM planes
    ln_dft<<<32768, 128>>>(ON, x, gamma, beta, Rh, Rl, Ih, Il);
    // FFT MLP layer 1 (gelu, 2-term) -> H2 planes
    gemm_pl<<<dim3(2, 1792, 1), 256, 65536>>>(Rh, W1Ah, B1A, (void*)H2h,
        128, 128, 128, 512, 256, 1.f, 2, 1, 2, 29360128LL, 32768LL, 117440512LL, 0, 0, 0);
    gemm_pl<<<dim3(2, 1792, 1), 256, 65536>>>(Ih, W1Bh, B1B, (void*)(H2h + 128),
        128, 128, 128, 512, 256, 1.f, 2, 1, 2, 29360128LL, 32768LL, 117440512LL, 0, 0, 0);
    // FFT MLP layer 2 (2-term) -> HR/HI f32
    gemm_pl<<<dim3(1, 1792, 1), 256, 65536>>>(H2h, WCRh, BCR, (void*)HR,
        256, 512, 256, 128, 128, 1.f, 0, 0, 2, 117440512LL, 32768LL, 0, 0, 0, 0);
    gemm_pl<<<dim3(1, 1792, 1), 256, 65536>>>(H2h + 256, WCIh, BCI, (void*)HI,
        256, 512, 256, 128, 128, 1.f, 0, 0, 2, 117440512LL, 32768LL, 0, 0, 0, 0);
    // irfft + residual
    irfft12<<<16384, 256>>>(HR, HI, x, out);
}